// round 1
// baseline (speedup 1.0000x reference)
#include <cuda_runtime.h>
#include <math.h>

// Problem constants
#define SQ   1024      // S (queries)
#define MEM  1024      // M (memory length)
#define NB   4         // batch
#define DM   1024      // d_model
#define NH   16        // heads
#define DH   64        // head dim
#define TT   2048      // T = S + M
#define SCALE 0.125f   // 1/sqrt(64)

// ---------------- scratch (static device globals; allocation-free) -------------
__device__ float g_qu[(size_t)NB*NH*SQ*DH];     // q + pos_bias_u, [b,h,i,dh]  16MB
__device__ float g_qv[(size_t)NB*NH*SQ*DH];     // q + pos_bias_v              16MB
__device__ float g_k [(size_t)NB*NH*TT*DH];     // [b,h,t,dh]                  32MB
__device__ float g_v [(size_t)NB*NH*TT*DH];     // [b,h,t,dh]                  32MB
__device__ float g_r [(size_t)NH*TT*DH];        // [h,p,dh]                     8MB
__device__ float g_scores[(size_t)NB*NH*SQ*TT]; // [b,h,i,j]                  512MB (reused for probs)
__device__ float g_avec[(size_t)SQ*NB*NH*DH];   // [i,b,h*dh]                  16MB
__device__ float g_aout[(size_t)SQ*NB*DM];      // [i,b,d]                     16MB

// ---------------- generic 128x128x16 fp32 GEMM with per-mode epilogue ----------
// MODE 0: qkv projection. A = concat(memory, x) rows n=t*B+b (8192 x 1024),
//         Bmat = W_qkv (1024 x 3072), scatter epilogue into g_qu/g_qv/g_k/g_v.
// MODE 1: rel projection. A = pos_emb (2048 x 1024), Bmat = W_rel (1024 x 1024),
//         scatter into g_r[h,p,dh].
// MODE 2: output projection. A = g_avec (4096 x 1024), Bmat = W_o, write g_aout.
template<int MODE>
__global__ void __launch_bounds__(256) gemm128(
    const float* __restrict__ A, const float* __restrict__ A2,
    const float* __restrict__ Bmat,
    const float* __restrict__ bu, const float* __restrict__ bv)
{
    constexpr int NCOLS = (MODE == 0) ? 3072 : 1024;
    constexpr int K = 1024;
    __shared__ float As[16][128];
    __shared__ float Bs[16][128];

    const int row0 = blockIdx.y * 128;
    const int col0 = blockIdx.x * 128;
    const int tid = threadIdx.x;
    const int ty = tid >> 4, tx = tid & 15;

    float acc[8][8];
#pragma unroll
    for (int i = 0; i < 8; i++)
#pragma unroll
        for (int j = 0; j < 8; j++) acc[i][j] = 0.f;

    const int lr = tid >> 2;          // 0..63
    const int lc = (tid & 3) << 2;    // 0,4,8,12
    const int br_ = tid >> 5;         // 0..7
    const int bc = (tid & 31) << 2;   // 0..124

    for (int k0 = 0; k0 < K; k0 += 16) {
#pragma unroll
        for (int p = 0; p < 2; p++) {
            int r = row0 + lr + p * 64;
            const float* src;
            if (MODE == 0) src = (r < MEM * NB) ? (A + (size_t)r * K)
                                                : (A2 + (size_t)(r - MEM * NB) * K);
            else if (MODE == 1) src = A + (size_t)r * K;
            else src = g_avec + (size_t)r * K;
            float4 a4 = *(const float4*)(src + k0 + lc);
            As[lc + 0][lr + p * 64] = a4.x;
            As[lc + 1][lr + p * 64] = a4.y;
            As[lc + 2][lr + p * 64] = a4.z;
            As[lc + 3][lr + p * 64] = a4.w;
        }
#pragma unroll
        for (int p = 0; p < 2; p++) {
            int r = k0 + br_ + p * 8;
            float4 b4 = *(const float4*)(Bmat + (size_t)r * NCOLS + col0 + bc);
            *(float4*)&Bs[br_ + p * 8][bc] = b4;
        }
        __syncthreads();
#pragma unroll
        for (int kk = 0; kk < 16; kk++) {
            float ar[8], brg[8];
#pragma unroll
            for (int i = 0; i < 8; i++) ar[i] = As[kk][ty * 8 + i];
#pragma unroll
            for (int j = 0; j < 8; j++) brg[j] = Bs[kk][tx * 8 + j];
#pragma unroll
            for (int i = 0; i < 8; i++)
#pragma unroll
                for (int j = 0; j < 8; j++) acc[i][j] += ar[i] * brg[j];
        }
        __syncthreads();
    }

    // epilogue
#pragma unroll
    for (int i = 0; i < 8; i++) {
        int n = row0 + ty * 8 + i;
#pragma unroll
        for (int j = 0; j < 8; j++) {
            int col = col0 + tx * 8 + j;
            float val = acc[i][j];
            if (MODE == 0) {
                int t = n >> 2, b = n & 3;
                int which = col >> 10;
                int hc = col & 1023;
                int h = hc >> 6, dh = hc & 63;
                if (which == 0) {
                    if (t >= MEM) {
                        size_t idx = (((size_t)(b * NH + h)) * SQ + (t - MEM)) * DH + dh;
                        g_qu[idx] = val + bu[hc];
                        g_qv[idx] = val + bv[hc];
                    }
                } else {
                    size_t idx = (((size_t)(b * NH + h)) * TT + t) * DH + dh;
                    if (which == 1) g_k[idx] = val; else g_v[idx] = val;
                }
            } else if (MODE == 1) {
                int h = col >> 6, dh = col & 63;
                g_r[((size_t)h * TT + n) * DH + dh] = val;
            } else {
                g_aout[(size_t)n * DM + col] = val;
            }
        }
    }
}

// ---------------- score kernel: AC + shifted BD, masked, 128x128 tiles ---------
// score[i,j] = (qu_i . k_j) + (qv_i . r_{j-i+S-1}), *scale, -1e30 where j > i+M
__global__ void __launch_bounds__(256) score_kernel()
{
    __shared__ float squ[16][128];
    __shared__ float sqv[16][128];
    __shared__ float sk [16][128];
    __shared__ float sr [16][256];

    const int bh = blockIdx.z;           // b*NH + h
    const int h  = bh & (NH - 1);
    const int i0 = blockIdx.y * 128;
    const int j0 = blockIdx.x * 128;
    const int tid = threadIdx.x;
    const int ty = tid >> 4, tx = tid & 15;
    const size_t srow = (size_t)bh * SQ * TT;

    if (j0 >= i0 + MEM + 128) {
        // tile entirely masked
        const float4 m4 = make_float4(-1e30f, -1e30f, -1e30f, -1e30f);
#pragma unroll
        for (int i = 0; i < 8; i++) {
            int gi = i0 + ty * 8 + i;
            float* dst = g_scores + srow + (size_t)gi * TT + j0 + tx * 8;
            *(float4*)(dst + 0) = m4;
            *(float4*)(dst + 4) = m4;
        }
        return;
    }

    const float* qu = g_qu + (size_t)bh * SQ * DH;
    const float* qv = g_qv + (size_t)bh * SQ * DH;
    const float* kp = g_k  + (size_t)bh * TT * DH;
    const float* rp = g_r  + (size_t)h  * TT * DH;
    const int pbase = j0 - i0 + (SQ - 128);  // p_global = pbase + p_local, p_local in [0,255)

    float acc[8][8];
#pragma unroll
    for (int i = 0; i < 8; i++)
#pragma unroll
        for (int j = 0; j < 8; j++) acc[i][j] = 0.f;

    const int lr = tid >> 2;
    const int lc = (tid & 3) << 2;

    for (int k0 = 0; k0 < DH; k0 += 16) {
#pragma unroll
        for (int p = 0; p < 2; p++) {
            int r = lr + p * 64;
            float4 a = *(const float4*)(qu + (size_t)(i0 + r) * DH + k0 + lc);
            squ[lc + 0][r] = a.x; squ[lc + 1][r] = a.y; squ[lc + 2][r] = a.z; squ[lc + 3][r] = a.w;
            float4 b = *(const float4*)(qv + (size_t)(i0 + r) * DH + k0 + lc);
            sqv[lc + 0][r] = b.x; sqv[lc + 1][r] = b.y; sqv[lc + 2][r] = b.z; sqv[lc + 3][r] = b.w;
            float4 c = *(const float4*)(kp + (size_t)(j0 + r) * DH + k0 + lc);
            sk[lc + 0][r] = c.x; sk[lc + 1][r] = c.y; sk[lc + 2][r] = c.z; sk[lc + 3][r] = c.w;
        }
#pragma unroll
        for (int p = 0; p < 4; p++) {
            int r = lr + p * 64;
            int pg = pbase + r;
            float4 c = make_float4(0.f, 0.f, 0.f, 0.f);
            if (pg < TT) c = *(const float4*)(rp + (size_t)pg * DH + k0 + lc);
            sr[lc + 0][r] = c.x; sr[lc + 1][r] = c.y; sr[lc + 2][r] = c.z; sr[lc + 3][r] = c.w;
        }
        __syncthreads();
#pragma unroll
        for (int kk = 0; kk < 16; kk++) {
            float au[8], av[8], bk[8], rv[15];
#pragma unroll
            for (int i = 0; i < 8; i++) { au[i] = squ[kk][ty * 8 + i]; av[i] = sqv[kk][ty * 8 + i]; }
#pragma unroll
            for (int j = 0; j < 8; j++) bk[j] = sk[kk][tx * 8 + j];
            const int pb = tx * 8 - ty * 8 + 120;   // rv[t] = sr[kk][pb + t], t in [0,14]
#pragma unroll
            for (int t = 0; t < 15; t++) rv[t] = sr[kk][pb + t];
#pragma unroll
            for (int i = 0; i < 8; i++)
#pragma unroll
                for (int j = 0; j < 8; j++)
                    acc[i][j] += au[i] * bk[j] + av[i] * rv[j - i + 7];
        }
        __syncthreads();
    }

    // mask + scale + write
#pragma unroll
    for (int i = 0; i < 8; i++) {
        int gi = i0 + ty * 8 + i;
        float vals[8];
#pragma unroll
        for (int j = 0; j < 8; j++) {
            int gj = j0 + tx * 8 + j;
            float vv = acc[i][j] * SCALE;
            vals[j] = (gj > gi + MEM) ? -1e30f : vv;
        }
        float* dst = g_scores + srow + (size_t)gi * TT + j0 + tx * 8;
        *(float4*)(dst + 0) = make_float4(vals[0], vals[1], vals[2], vals[3]);
        *(float4*)(dst + 4) = make_float4(vals[4], vals[5], vals[6], vals[7]);
    }
}

// ---------------- softmax over j (in-place on g_scores) ------------------------
__global__ void __launch_bounds__(256) softmax_kernel()
{
    __shared__ float sh[8];
    float* p = g_scores + (size_t)blockIdx.x * TT;
    const int tid = threadIdx.x;

    float4 v0 = ((float4*)p)[tid];
    float4 v1 = ((float4*)p)[tid + 256];

    float m = fmaxf(fmaxf(fmaxf(v0.x, v0.y), fmaxf(v0.z, v0.w)),
                    fmaxf(fmaxf(v1.x, v1.y), fmaxf(v1.z, v1.w)));
#pragma unroll
    for (int o = 16; o > 0; o >>= 1) m = fmaxf(m, __shfl_xor_sync(0xffffffffu, m, o));
    if ((tid & 31) == 0) sh[tid >> 5] = m;
    __syncthreads();
    if (tid < 8) {
        float t = sh[tid];
#pragma unroll
        for (int o = 4; o > 0; o >>= 1) t = fmaxf(t, __shfl_xor_sync(0xffu, t, o));
        if (tid == 0) sh[0] = t;
    }
    __syncthreads();
    m = sh[0];
    __syncthreads();

    v0.x = expf(v0.x - m); v0.y = expf(v0.y - m); v0.z = expf(v0.z - m); v0.w = expf(v0.w - m);
    v1.x = expf(v1.x - m); v1.y = expf(v1.y - m); v1.z = expf(v1.z - m); v1.w = expf(v1.w - m);
    float s = v0.x + v0.y + v0.z + v0.w + v1.x + v1.y + v1.z + v1.w;
#pragma unroll
    for (int o = 16; o > 0; o >>= 1) s += __shfl_xor_sync(0xffffffffu, s, o);
    if ((tid & 31) == 0) sh[tid >> 5] = s;
    __syncthreads();
    if (tid < 8) {
        float t = sh[tid];
#pragma unroll
        for (int o = 4; o > 0; o >>= 1) t += __shfl_xor_sync(0xffu, t, o);
        if (tid == 0) sh[0] = t;
    }
    __syncthreads();
    const float inv = 1.0f / sh[0];

    v0.x *= inv; v0.y *= inv; v0.z *= inv; v0.w *= inv;
    v1.x *= inv; v1.y *= inv; v1.z *= inv; v1.w *= inv;
    ((float4*)p)[tid] = v0;
    ((float4*)p)[tid + 256] = v1;
}

// ---------------- P @ V per (b,h), causally trimmed K loop ---------------------
__global__ void __launch_bounds__(256) pv_kernel()
{
    __shared__ float sp[32][64];   // [j_local][i_local]
    __shared__ float sv[32][64];   // [j_local][dh]

    const int bh = blockIdx.z;
    const int b = bh >> 4, h = bh & 15;
    const int i0 = blockIdx.y * 64;
    const float* P = g_scores + (size_t)bh * SQ * TT;
    const float* V = g_v + (size_t)bh * TT * DH;
    const int kend = min(TT, i0 + 64 + MEM);

    const int tid = threadIdx.x;
    const int ty = tid >> 4, tx = tid & 15;

    float acc[4][4];
#pragma unroll
    for (int i = 0; i < 4; i++)
#pragma unroll
        for (int j = 0; j < 4; j++) acc[i][j] = 0.f;

    const int plr = tid >> 3;            // 0..31
    const int plc = (tid & 7) << 2;      // 0..28
    const int vlr = tid >> 4;            // 0..15
    const int vlc = (tid & 15) << 2;     // 0..60

    for (int k0 = 0; k0 < kend; k0 += 32) {
#pragma unroll
        for (int p = 0; p < 2; p++) {
            int r = plr + p * 32;        // i_local 0..63
            float4 a = *(const float4*)(P + (size_t)(i0 + r) * TT + k0 + plc);
            sp[plc + 0][r] = a.x; sp[plc + 1][r] = a.y; sp[plc + 2][r] = a.z; sp[plc + 3][r] = a.w;
        }
#pragma unroll
        for (int p = 0; p < 2; p++) {
            int r = vlr + p * 16;        // j_local 0..31
            *(float4*)&sv[r][vlc] = *(const float4*)(V + (size_t)(k0 + r) * DH + vlc);
        }
        __syncthreads();
#pragma unroll
        for (int kk = 0; kk < 32; kk++) {
            float a[4], c[4];
#pragma unroll
            for (int i = 0; i < 4; i++) a[i] = sp[kk][ty * 4 + i];
#pragma unroll
            for (int j = 0; j < 4; j++) c[j] = sv[kk][tx * 4 + j];
#pragma unroll
            for (int i = 0; i < 4; i++)
#pragma unroll
                for (int j = 0; j < 4; j++) acc[i][j] += a[i] * c[j];
        }
        __syncthreads();
    }

#pragma unroll
    for (int i = 0; i < 4; i++) {
        int gi = i0 + ty * 4 + i;
        float* dst = g_avec + ((size_t)gi * NB + b) * (NH * DH) + h * DH + tx * 4;
        *(float4*)dst = make_float4(acc[i][0], acc[i][1], acc[i][2], acc[i][3]);
    }
}

// ---------------- residual + LayerNorm -----------------------------------------
__global__ void __launch_bounds__(256) ln_kernel(
    const float* __restrict__ x, const float* __restrict__ gamma,
    const float* __restrict__ beta, float* __restrict__ out)
{
    __shared__ float shs[8], shss[8];
    const int n = blockIdx.x;
    const int tid = threadIdx.x;
    const float* xr = x + (size_t)n * DM;
    const float* ar = g_aout + (size_t)n * DM;

    float vals[4];
    float s = 0.f, ss = 0.f;
#pragma unroll
    for (int q = 0; q < 4; q++) {
        int d = tid + q * 256;
        float y = xr[d] + ar[d];
        vals[q] = y; s += y; ss += y * y;
    }
#pragma unroll
    for (int o = 16; o > 0; o >>= 1) {
        s += __shfl_xor_sync(0xffffffffu, s, o);
        ss += __shfl_xor_sync(0xffffffffu, ss, o);
    }
    if ((tid & 31) == 0) { shs[tid >> 5] = s; shss[tid >> 5] = ss; }
    __syncthreads();
    if (tid < 8) {
        float t1 = shs[tid], t2 = shss[tid];
#pragma unroll
        for (int o = 4; o > 0; o >>= 1) {
            t1 += __shfl_xor_sync(0xffu, t1, o);
            t2 += __shfl_xor_sync(0xffu, t2, o);
        }
        if (tid == 0) { shs[0] = t1; shss[0] = t2; }
    }
    __syncthreads();
    const float mu = shs[0] * (1.0f / DM);
    const float var = shss[0] * (1.0f / DM) - mu * mu;
    const float inv = rsqrtf(var + 1e-5f);

    float* orow = out + (size_t)n * DM;
#pragma unroll
    for (int q = 0; q < 4; q++) {
        int d = tid + q * 256;
        orow[d] = (vals[q] - mu) * inv * gamma[d] + beta[d];
    }
}

// ---------------- launch ---------------------------------------------------------
extern "C" void kernel_launch(void* const* d_in, const int* in_sizes, int n_in,
                              void* d_out, int out_size)
{
    (void)in_sizes; (void)n_in; (void)out_size;
    const float* x       = (const float*)d_in[0];   // [S,B,D]
    const float* pos_emb = (const float*)d_in[1];   // [T,D]
    const float* bu      = (const float*)d_in[2];   // [H,DH]
    const float* bv      = (const float*)d_in[3];   // [H,DH]
    const float* memory  = (const float*)d_in[4];   // [M,B,D]
    const float* W_qkv   = (const float*)d_in[5];   // [D,3*H*DH]
    const float* W_rel   = (const float*)d_in[6];   // [D,H*DH]
    const float* W_o     = (const float*)d_in[7];   // [H*DH,D]
    const float* gamma   = (const float*)d_in[8];   // [D]
    const float* beta    = (const float*)d_in[9];   // [D]
    // d_in[10] = mask: ignored (computed analytically; rel_shift garbage == masked region)
    float* out = (float*)d_out;

    // 1. QKV projection (concat(memory,x) @ W_qkv) with bias scatter
    gemm128<0><<<dim3(24, 64), 256>>>(memory, x, W_qkv, bu, bv);
    // 2. positional projection (pos_emb @ W_rel)
    gemm128<1><<<dim3(8, 16), 256>>>(pos_emb, nullptr, W_rel, nullptr, nullptr);
    // 3. fused AC + rel-shifted BD scores, masked & scaled
    score_kernel<<<dim3(TT / 128, SQ / 128, NB * NH), 256>>>();
    // 4. softmax over keys (in place)
    softmax_kernel<<<NB * NH * SQ, 256>>>();
    // 5. attention @ V
    pv_kernel<<<dim3(1, SQ / 64, NB * NH), 256>>>();
    // 6. output projection
    gemm128<2><<<dim3(8, 32), 256>>>(nullptr, nullptr, W_o, nullptr, nullptr);
    // 7. residual + LayerNorm
    ln_kernel<<<SQ * NB, 256>>>(x, gamma, beta, out);
}

// round 3
// speedup vs baseline: 1.0022x; 1.0022x over previous
#include <cuda_runtime.h>
#include <math.h>

// Problem constants
#define SQ   1024      // S (queries)
#define MEM  1024      // M (memory length)
#define NB   4         // batch
#define DM   1024      // d_model
#define NH   16        // heads
#define DH   64        // head dim
#define TT   2048      // T = S + M
#define SCALE 0.125f   // 1/sqrt(64)

// ---------------- scratch (static device globals; allocation-free) -------------
__device__ float g_qu[(size_t)NB*NH*SQ*DH];     // q + pos_bias_u, [b,h,i,dh]  16MB
__device__ float g_qv[(size_t)NB*NH*SQ*DH];     // q + pos_bias_v              16MB
__device__ float g_k [(size_t)NB*NH*TT*DH];     // [b,h,t,dh]                  32MB
__device__ float g_v [(size_t)NB*NH*TT*DH];     // [b,h,t,dh]                  32MB
__device__ float g_r [(size_t)NH*TT*DH];        // [h,p,dh]                     8MB
__device__ float g_scores[(size_t)NB*NH*SQ*TT]; // [b,h,i,j]                  512MB (reused for probs)
__device__ float g_avec[(size_t)SQ*NB*NH*DH];   // [i,b,h*dh]                  16MB
__device__ float g_aout[(size_t)SQ*NB*DM];      // [i,b,d]                     16MB

// ---------------- generic 128x128x16 fp32 GEMM with per-mode epilogue ----------
// MODE 0: qkv projection. A = concat(memory, x) rows n=t*B+b (8192 x 1024),
//         Bmat = W_qkv (1024 x 3072), scatter epilogue into g_qu/g_qv/g_k/g_v.
// MODE 1: rel projection. A = pos_emb (2048 x 1024), Bmat = W_rel (1024 x 1024),
//         scatter into g_r[h,p,dh].
// MODE 2: output projection. A = g_avec (4096 x 1024), Bmat = W_o, write g_aout.
template<int MODE>
__global__ void __launch_bounds__(256) gemm128(
    const float* __restrict__ A, const float* __restrict__ A2,
    const float* __restrict__ Bmat,
    const float* __restrict__ bu, const float* __restrict__ bv)
{
    constexpr int NCOLS = (MODE == 0) ? 3072 : 1024;
    constexpr int K = 1024;
    __shared__ float As[16][128];
    __shared__ float Bs[16][128];

    const int row0 = blockIdx.y * 128;
    const int col0 = blockIdx.x * 128;
    const int tid = threadIdx.x;
    const int ty = tid >> 4, tx = tid & 15;

    float acc[8][8];
#pragma unroll
    for (int i = 0; i < 8; i++)
#pragma unroll
        for (int j = 0; j < 8; j++) acc[i][j] = 0.f;

    const int lr = tid >> 2;          // 0..63
    const int lc = (tid & 3) << 2;    // 0,4,8,12
    const int br_ = tid >> 5;         // 0..7
    const int bc = (tid & 31) << 2;   // 0..124

    for (int k0 = 0; k0 < K; k0 += 16) {
#pragma unroll
        for (int p = 0; p < 2; p++) {
            int r = row0 + lr + p * 64;
            const float* src;
            if (MODE == 0) src = (r < MEM * NB) ? (A + (size_t)r * K)
                                                : (A2 + (size_t)(r - MEM * NB) * K);
            else if (MODE == 1) src = A + (size_t)r * K;
            else src = g_avec + (size_t)r * K;
            float4 a4 = *(const float4*)(src + k0 + lc);
            As[lc + 0][lr + p * 64] = a4.x;
            As[lc + 1][lr + p * 64] = a4.y;
            As[lc + 2][lr + p * 64] = a4.z;
            As[lc + 3][lr + p * 64] = a4.w;
        }
#pragma unroll
        for (int p = 0; p < 2; p++) {
            int r = k0 + br_ + p * 8;
            float4 b4 = *(const float4*)(Bmat + (size_t)r * NCOLS + col0 + bc);
            *(float4*)&Bs[br_ + p * 8][bc] = b4;
        }
        __syncthreads();
#pragma unroll
        for (int kk = 0; kk < 16; kk++) {
            float ar[8], brg[8];
#pragma unroll
            for (int i = 0; i < 8; i++) ar[i] = As[kk][ty * 8 + i];
#pragma unroll
            for (int j = 0; j < 8; j++) brg[j] = Bs[kk][tx * 8 + j];
#pragma unroll
            for (int i = 0; i < 8; i++)
#pragma unroll
                for (int j = 0; j < 8; j++) acc[i][j] += ar[i] * brg[j];
        }
        __syncthreads();
    }

    // epilogue
#pragma unroll
    for (int i = 0; i < 8; i++) {
        int n = row0 + ty * 8 + i;
#pragma unroll
        for (int j = 0; j < 8; j++) {
            int col = col0 + tx * 8 + j;
            float val = acc[i][j];
            if (MODE == 0) {
                int t = n >> 2, b = n & 3;
                int which = col >> 10;
                int hc = col & 1023;
                int h = hc >> 6, dh = hc & 63;
                if (which == 0) {
                    if (t >= MEM) {
                        size_t idx = (((size_t)(b * NH + h)) * SQ + (t - MEM)) * DH + dh;
                        g_qu[idx] = val + bu[hc];
                        g_qv[idx] = val + bv[hc];
                    }
                } else {
                    size_t idx = (((size_t)(b * NH + h)) * TT + t) * DH + dh;
                    if (which == 1) g_k[idx] = val; else g_v[idx] = val;
                }
            } else if (MODE == 1) {
                int h = col >> 6, dh = col & 63;
                g_r[((size_t)h * TT + n) * DH + dh] = val;
            } else {
                g_aout[(size_t)n * DM + col] = val;
            }
        }
    }
}

// ---------------- score kernel: AC + shifted BD, masked, 128x128 tiles ---------
// score[i,j] = (qu_i . k_j) + (qv_i . r_{j-i+S-1}), *scale, -1e30 where j > i+M
__global__ void __launch_bounds__(256) score_kernel()
{
    __shared__ float squ[16][128];
    __shared__ float sqv[16][128];
    __shared__ float sk [16][128];
    __shared__ float sr [16][256];

    const int bh = blockIdx.z;           // b*NH + h
    const int h  = bh & (NH - 1);
    const int i0 = blockIdx.y * 128;
    const int j0 = blockIdx.x * 128;
    const int tid = threadIdx.x;
    const int ty = tid >> 4, tx = tid & 15;
    const size_t srow = (size_t)bh * SQ * TT;

    if (j0 >= i0 + MEM + 128) {
        // tile entirely masked
        const float4 m4 = make_float4(-1e30f, -1e30f, -1e30f, -1e30f);
#pragma unroll
        for (int i = 0; i < 8; i++) {
            int gi = i0 + ty * 8 + i;
            float* dst = g_scores + srow + (size_t)gi * TT + j0 + tx * 8;
            *(float4*)(dst + 0) = m4;
            *(float4*)(dst + 4) = m4;
        }
        return;
    }

    const float* qu = g_qu + (size_t)bh * SQ * DH;
    const float* qv = g_qv + (size_t)bh * SQ * DH;
    const float* kp = g_k  + (size_t)bh * TT * DH;
    const float* rp = g_r  + (size_t)h  * TT * DH;
    const int pbase = j0 - i0 + (SQ - 128);  // p_global = pbase + p_local, p_local in [0,255)

    float acc[8][8];
#pragma unroll
    for (int i = 0; i < 8; i++)
#pragma unroll
        for (int j = 0; j < 8; j++) acc[i][j] = 0.f;

    const int lr = tid >> 2;
    const int lc = (tid & 3) << 2;

    for (int k0 = 0; k0 < DH; k0 += 16) {
#pragma unroll
        for (int p = 0; p < 2; p++) {
            int r = lr + p * 64;
            float4 a = *(const float4*)(qu + (size_t)(i0 + r) * DH + k0 + lc);
            squ[lc + 0][r] = a.x; squ[lc + 1][r] = a.y; squ[lc + 2][r] = a.z; squ[lc + 3][r] = a.w;
            float4 b = *(const float4*)(qv + (size_t)(i0 + r) * DH + k0 + lc);
            sqv[lc + 0][r] = b.x; sqv[lc + 1][r] = b.y; sqv[lc + 2][r] = b.z; sqv[lc + 3][r] = b.w;
            float4 c = *(const float4*)(kp + (size_t)(j0 + r) * DH + k0 + lc);
            sk[lc + 0][r] = c.x; sk[lc + 1][r] = c.y; sk[lc + 2][r] = c.z; sk[lc + 3][r] = c.w;
        }
#pragma unroll
        for (int p = 0; p < 4; p++) {
            int r = lr + p * 64;
            int pg = pbase + r;
            float4 c = make_float4(0.f, 0.f, 0.f, 0.f);
            if (pg < TT) c = *(const float4*)(rp + (size_t)pg * DH + k0 + lc);
            sr[lc + 0][r] = c.x; sr[lc + 1][r] = c.y; sr[lc + 2][r] = c.z; sr[lc + 3][r] = c.w;
        }
        __syncthreads();
#pragma unroll
        for (int kk = 0; kk < 16; kk++) {
            float au[8], av[8], bk[8], rv[15];
#pragma unroll
            for (int i = 0; i < 8; i++) { au[i] = squ[kk][ty * 8 + i]; av[i] = sqv[kk][ty * 8 + i]; }
#pragma unroll
            for (int j = 0; j < 8; j++) bk[j] = sk[kk][tx * 8 + j];
            const int pb = tx * 8 - ty * 8 + 120;   // rv[t] = sr[kk][pb + t], t in [0,14]
#pragma unroll
            for (int t = 0; t < 15; t++) rv[t] = sr[kk][pb + t];
#pragma unroll
            for (int i = 0; i < 8; i++)
#pragma unroll
                for (int j = 0; j < 8; j++)
                    acc[i][j] += au[i] * bk[j] + av[i] * rv[j - i + 7];
        }
        __syncthreads();
    }

    // mask + scale + write
#pragma unroll
    for (int i = 0; i < 8; i++) {
        int gi = i0 + ty * 8 + i;
        float vals[8];
#pragma unroll
        for (int j = 0; j < 8; j++) {
            int gj = j0 + tx * 8 + j;
            float vv = acc[i][j] * SCALE;
            vals[j] = (gj > gi + MEM) ? -1e30f : vv;
        }
        float* dst = g_scores + srow + (size_t)gi * TT + j0 + tx * 8;
        *(float4*)(dst + 0) = make_float4(vals[0], vals[1], vals[2], vals[3]);
        *(float4*)(dst + 4) = make_float4(vals[4], vals[5], vals[6], vals[7]);
    }
}

// ---------------- softmax over j (in-place on g_scores) ------------------------
__global__ void __launch_bounds__(256) softmax_kernel()
{
    __shared__ float sh[8];
    float* p = g_scores + (size_t)blockIdx.x * TT;
    const int tid = threadIdx.x;

    float4 v0 = ((float4*)p)[tid];
    float4 v1 = ((float4*)p)[tid + 256];

    float m = fmaxf(fmaxf(fmaxf(v0.x, v0.y), fmaxf(v0.z, v0.w)),
                    fmaxf(fmaxf(v1.x, v1.y), fmaxf(v1.z, v1.w)));
#pragma unroll
    for (int o = 16; o > 0; o >>= 1) m = fmaxf(m, __shfl_xor_sync(0xffffffffu, m, o));
    if ((tid & 31) == 0) sh[tid >> 5] = m;
    __syncthreads();
    if (tid < 8) {
        float t = sh[tid];
#pragma unroll
        for (int o = 4; o > 0; o >>= 1) t = fmaxf(t, __shfl_xor_sync(0xffu, t, o));
        if (tid == 0) sh[0] = t;
    }
    __syncthreads();
    m = sh[0];
    __syncthreads();

    v0.x = expf(v0.x - m); v0.y = expf(v0.y - m); v0.z = expf(v0.z - m); v0.w = expf(v0.w - m);
    v1.x = expf(v1.x - m); v1.y = expf(v1.y - m); v1.z = expf(v1.z - m); v1.w = expf(v1.w - m);
    float s = v0.x + v0.y + v0.z + v0.w + v1.x + v1.y + v1.z + v1.w;
#pragma unroll
    for (int o = 16; o > 0; o >>= 1) s += __shfl_xor_sync(0xffffffffu, s, o);
    if ((tid & 31) == 0) sh[tid >> 5] = s;
    __syncthreads();
    if (tid < 8) {
        float t = sh[tid];
#pragma unroll
        for (int o = 4; o > 0; o >>= 1) t += __shfl_xor_sync(0xffu, t, o);
        if (tid == 0) sh[0] = t;
    }
    __syncthreads();
    const float inv = 1.0f / sh[0];

    v0.x *= inv; v0.y *= inv; v0.z *= inv; v0.w *= inv;
    v1.x *= inv; v1.y *= inv; v1.z *= inv; v1.w *= inv;
    ((float4*)p)[tid] = v0;
    ((float4*)p)[tid + 256] = v1;
}

// ---------------- P @ V per (b,h), causally trimmed K loop ---------------------
__global__ void __launch_bounds__(256) pv_kernel()
{
    __shared__ float sp[32][64];   // [j_local][i_local]
    __shared__ float sv[32][64];   // [j_local][dh]

    const int bh = blockIdx.z;
    const int b = bh >> 4, h = bh & 15;
    const int i0 = blockIdx.y * 64;
    const float* P = g_scores + (size_t)bh * SQ * TT;
    const float* V = g_v + (size_t)bh * TT * DH;
    const int kend = min(TT, i0 + 64 + MEM);

    const int tid = threadIdx.x;
    const int ty = tid >> 4, tx = tid & 15;

    float acc[4][4];
#pragma unroll
    for (int i = 0; i < 4; i++)
#pragma unroll
        for (int j = 0; j < 4; j++) acc[i][j] = 0.f;

    const int plr = tid >> 3;            // 0..31
    const int plc = (tid & 7) << 2;      // 0..28
    const int vlr = tid >> 4;            // 0..15
    const int vlc = (tid & 15) << 2;     // 0..60

    for (int k0 = 0; k0 < kend; k0 += 32) {
#pragma unroll
        for (int p = 0; p < 2; p++) {
            int r = plr + p * 32;        // i_local 0..63
            float4 a = *(const float4*)(P + (size_t)(i0 + r) * TT + k0 + plc);
            sp[plc + 0][r] = a.x; sp[plc + 1][r] = a.y; sp[plc + 2][r] = a.z; sp[plc + 3][r] = a.w;
        }
#pragma unroll
        for (int p = 0; p < 2; p++) {
            int r = vlr + p * 16;        // j_local 0..31
            *(float4*)&sv[r][vlc] = *(const float4*)(V + (size_t)(k0 + r) * DH + vlc);
        }
        __syncthreads();
#pragma unroll
        for (int kk = 0; kk < 32; kk++) {
            float a[4], c[4];
#pragma unroll
            for (int i = 0; i < 4; i++) a[i] = sp[kk][ty * 4 + i];
#pragma unroll
            for (int j = 0; j < 4; j++) c[j] = sv[kk][tx * 4 + j];
#pragma unroll
            for (int i = 0; i < 4; i++)
#pragma unroll
                for (int j = 0; j < 4; j++) acc[i][j] += a[i] * c[j];
        }
        __syncthreads();
    }

#pragma unroll
    for (int i = 0; i < 4; i++) {
        int gi = i0 + ty * 4 + i;
        float* dst = g_avec + ((size_t)gi * NB + b) * (NH * DH) + h * DH + tx * 4;
        *(float4*)dst = make_float4(acc[i][0], acc[i][1], acc[i][2], acc[i][3]);
    }
}

// ---------------- residual + LayerNorm -----------------------------------------
__global__ void __launch_bounds__(256) ln_kernel(
    const float* __restrict__ x, const float* __restrict__ gamma,
    const float* __restrict__ beta, float* __restrict__ out)
{
    __shared__ float shs[8], shss[8];
    const int n = blockIdx.x;
    const int tid = threadIdx.x;
    const float* xr = x + (size_t)n * DM;
    const float* ar = g_aout + (size_t)n * DM;

    float vals[4];
    float s = 0.f, ss = 0.f;
#pragma unroll
    for (int q = 0; q < 4; q++) {
        int d = tid + q * 256;
        float y = xr[d] + ar[d];
        vals[q] = y; s += y; ss += y * y;
    }
#pragma unroll
    for (int o = 16; o > 0; o >>= 1) {
        s += __shfl_xor_sync(0xffffffffu, s, o);
        ss += __shfl_xor_sync(0xffffffffu, ss, o);
    }
    if ((tid & 31) == 0) { shs[tid >> 5] = s; shss[tid >> 5] = ss; }
    __syncthreads();
    if (tid < 8) {
        float t1 = shs[tid], t2 = shss[tid];
#pragma unroll
        for (int o = 4; o > 0; o >>= 1) {
            t1 += __shfl_xor_sync(0xffu, t1, o);
            t2 += __shfl_xor_sync(0xffu, t2, o);
        }
        if (tid == 0) { shs[0] = t1; shss[0] = t2; }
    }
    __syncthreads();
    const float mu = shs[0] * (1.0f / DM);
    const float var = shss[0] * (1.0f / DM) - mu * mu;
    const float inv = rsqrtf(var + 1e-5f);

    float* orow = out + (size_t)n * DM;
#pragma unroll
    for (int q = 0; q < 4; q++) {
        int d = tid + q * 256;
        orow[d] = (vals[q] - mu) * inv * gamma[d] + beta[d];
    }
}

// ---------------- launch ---------------------------------------------------------
extern "C" void kernel_launch(void* const* d_in, const int* in_sizes, int n_in,
                              void* d_out, int out_size)
{
    (void)in_sizes; (void)n_in; (void)out_size;
    const float* x       = (const float*)d_in[0];   // [S,B,D]
    const float* pos_emb = (const float*)d_in[1];   // [T,D]
    const float* bu      = (const float*)d_in[2];   // [H,DH]
    const float* bv      = (const float*)d_in[3];   // [H,DH]
    const float* memory  = (const float*)d_in[4];   // [M,B,D]
    const float* W_qkv   = (const float*)d_in[5];   // [D,3*H*DH]
    const float* W_rel   = (const float*)d_in[6];   // [D,H*DH]
    const float* W_o     = (const float*)d_in[7];   // [H*DH,D]
    const float* gamma   = (const float*)d_in[8];   // [D]
    const float* beta    = (const float*)d_in[9];   // [D]
    // d_in[10] = mask: ignored (computed analytically; rel_shift garbage == masked region)
    float* out = (float*)d_out;

    // 1. QKV projection (concat(memory,x) @ W_qkv) with bias scatter
    gemm128<0><<<dim3(24, 64), 256>>>(memory, x, W_qkv, bu, bv);
    // 2. positional projection (pos_emb @ W_rel)
    gemm128<1><<<dim3(8, 16), 256>>>(pos_emb, nullptr, W_rel, nullptr, nullptr);
    // 3. fused AC + rel-shifted BD scores, masked & scaled
    score_kernel<<<dim3(TT / 128, SQ / 128, NB * NH), 256>>>();
    // 4. softmax over keys (in place)
    softmax_kernel<<<NB * NH * SQ, 256>>>();
    // 5. attention @ V
    pv_kernel<<<dim3(1, SQ / 64, NB * NH), 256>>>();
    // 6. output projection
    gemm128<2><<<dim3(8, 32), 256>>>(nullptr, nullptr, W_o, nullptr, nullptr);
    // 7. residual + LayerNorm
    ln_kernel<<<SQ * NB, 256>>>(x, gamma, beta, out);
}

// round 9
// speedup vs baseline: 2.3343x; 2.3290x over previous
#include <cuda_runtime.h>
#include <cuda_bf16.h>
#include <math.h>
#include <stdint.h>

#define SQ 1024
#define MEML 1024
#define DMODEL 1024

// ---------------- scratch (static device globals; allocation-free) -------------
__device__ __nv_bfloat16 c_bf  [(size_t)8192*1024];   // concat(memory,x), row n=t*4+b
__device__ __nv_bfloat16 pos_bf[(size_t)2048*1024];
__device__ __nv_bfloat16 wqkvT [(size_t)3072*1024];   // W_qkv^T
__device__ __nv_bfloat16 wrelT [(size_t)1024*1024];
__device__ __nv_bfloat16 woT   [(size_t)1024*1024];
__device__ __nv_bfloat16 g_qu  [(size_t)64*1024*64];  // [bh][i][dh]
__device__ __nv_bfloat16 g_qv  [(size_t)64*1024*64];
__device__ __nv_bfloat16 g_k   [(size_t)64*2048*64];  // [bh][t][dh]
__device__ __nv_bfloat16 g_vT  [(size_t)64*64*2048];  // [bh][dh][t]
__device__ __nv_bfloat16 g_r   [(size_t)16*2048*64];  // [h][p][dh]
__device__ float         g_AC  [(size_t)64*1024*2048];// [bh][i][j] final logits
__device__ float         g_BD  [(size_t)64*1024*2048];// [bh][i][p]
__device__ __nv_bfloat16 g_P   [(size_t)64*1024*2048];// [bh][i][j] probs
__device__ __nv_bfloat16 g_avec[(size_t)4096*1024];   // [i*4+b][h*64+dh]
__device__ float         g_aout[(size_t)4096*1024];

// ---------------- helpers -------------------------------------------------------
__device__ __forceinline__ uint32_t smem_u32(const void* p){
    uint32_t a;
    asm("{ .reg .u64 t; cvta.to.shared.u64 t, %1; cvt.u32.u64 %0, t; }" : "=r"(a) : "l"(p));
    return a;
}
__device__ __forceinline__ uint32_t pk2(float a, float b){
    return (uint32_t)__bfloat16_as_ushort(__float2bfloat16(a))
         | ((uint32_t)__bfloat16_as_ushort(__float2bfloat16(b)) << 16);
}
__device__ __forceinline__ void ldm_x4(uint32_t* r, uint32_t addr){
    asm volatile("ldmatrix.sync.aligned.m8n8.x4.shared.b16 {%0,%1,%2,%3}, [%4];"
        : "=r"(r[0]), "=r"(r[1]), "=r"(r[2]), "=r"(r[3]) : "r"(addr));
}
__device__ __forceinline__ void mma16816(float* c, const uint32_t* a, const uint32_t* b){
    asm volatile("mma.sync.aligned.m16n8k16.row.col.f32.bf16.bf16.f32 "
        "{%0,%1,%2,%3}, {%4,%5,%6,%7}, {%8,%9}, {%0,%1,%2,%3};"
        : "+f"(c[0]), "+f"(c[1]), "+f"(c[2]), "+f"(c[3])
        : "r"(a[0]), "r"(a[1]), "r"(a[2]), "r"(a[3]), "r"(b[0]), "r"(b[1]));
}

// ---------------- prep kernels --------------------------------------------------
__global__ void __launch_bounds__(256) conv_c(const float* __restrict__ mem, const float* __restrict__ x){
    size_t n = blockIdx.x;
    const float* src = (n < 4096) ? (mem + n*1024) : (x + (n-4096)*1024);
    __nv_bfloat16* dst = c_bf + n*1024;
#pragma unroll
    for (int q = 0; q < 4; q++){ int d = threadIdx.x + q*256; dst[d] = __float2bfloat16(src[d]); }
}
__global__ void __launch_bounds__(256) conv_pos(const float* __restrict__ pe){
    size_t n = blockIdx.x;
    const float* src = pe + n*1024;
    __nv_bfloat16* dst = pos_bf + n*1024;
#pragma unroll
    for (int q = 0; q < 4; q++){ int d = threadIdx.x + q*256; dst[d] = __float2bfloat16(src[d]); }
}
// transpose fp32 [1024][C] -> bf16 [C][1024]
__global__ void __launch_bounds__(256) transpose_bf(const float* __restrict__ src, int mode, int C){
    __shared__ float tile[32][33];
    __nv_bfloat16* dst = (mode == 0) ? wqkvT : (mode == 1) ? wrelT : woT;
    const int R = 1024;
    int c0 = blockIdx.x*32, r0 = blockIdx.y*32;
    int tx = threadIdx.x & 31, ty = threadIdx.x >> 5;
#pragma unroll
    for (int q = 0; q < 4; q++)
        tile[ty + q*8][tx] = src[(size_t)(r0 + ty + q*8)*C + c0 + tx];
    __syncthreads();
#pragma unroll
    for (int q = 0; q < 4; q++)
        dst[(size_t)(c0 + ty + q*8)*R + r0 + tx] = __float2bfloat16(tile[tx][ty + q*8]);
}

// ---------------- generic mma.sync GEMM -----------------------------------------
// MODE 0: QKV   c_bf(8192x1024) @ wqkvT^T(3072x1024)  -> scatter qu/qv/k/vT (bf16)
// MODE 1: REL   pos_bf(2048x1024) @ wrelT^T           -> g_r (bf16)
// MODE 2: AC    qu(1024x64) @ k^T(2048x64) per bh     -> logits = (AC + shifted BD)*scale (f32)
// MODE 3: BD    qv(1024x64) @ r^T(2048x64) per bh     -> g_BD (f32)
// MODE 4: PV    P(1024x2048) @ vT^T(64x2048) per bh   -> g_avec (bf16)
// MODE 5: OUT   avec(4096x1024) @ woT^T(1024x1024)    -> g_aout (f32)
template<int MODE>
__global__ void __launch_bounds__(256) gemm_tc(const float* __restrict__ bu, const float* __restrict__ bv)
{
    constexpr int KC = (MODE == 2 || MODE == 3) ? 64 : 128;
    constexpr int NT = (MODE == 4) ? 64 : 128;
    constexpr int NF = NT / 32;              // n-frags per warp (warp tile NT/4 cols)
    constexpr int SA = KC*2 + 16;            // smem row stride (bytes), conflict-free ldmatrix
    constexpr int ASZ = 128*SA;
    constexpr int BSZ = NT*SA;
    extern __shared__ char smem[];
    char* smB = smem + ASZ;
    float* stage = (float*)(smem + ASZ + BSZ);   // [128][NT+1]
    const uint32_t smA32 = smem_u32(smem);
    const uint32_t smB32 = smA32 + ASZ;

    const int tid = threadIdx.x;
    const int lane = tid & 31, wid = tid >> 5;
    const int wm = wid & 1, wn = wid >> 1;

    int m0, n0, bh = 0, h = 0, b = 0, nchunks;
    if (MODE == 0)      { m0 = blockIdx.y*128; n0 = blockIdx.x*128; nchunks = 8; }
    else if (MODE == 1) { m0 = blockIdx.y*128; n0 = blockIdx.x*128; nchunks = 8; }
    else if (MODE == 2) { bh = blockIdx.z; m0 = blockIdx.y*128; n0 = blockIdx.x*128;
                          if (n0 > m0 + 1151) return; nchunks = 1; }
    else if (MODE == 3) { bh = blockIdx.z; h = bh & 15; m0 = blockIdx.y*128; n0 = blockIdx.x*128;
                          if (n0 + m0 <= 768) return; nchunks = 1; }
    else if (MODE == 4) { bh = blockIdx.z; b = bh >> 4; h = bh & 15; m0 = blockIdx.y*128; n0 = 0;
                          nchunks = m0/128 + 9; }
    else                { m0 = blockIdx.y*128; n0 = blockIdx.x*128; nchunks = 8; }

    float acc[4][NF][4] = {};

    for (int ch = 0; ch < nchunks; ch++) {
        const int k0 = ch * KC;
        constexpr int RQ = KC/8;              // uint4 per smem row
        constexpr int APT = 128*RQ/256;
#pragma unroll
        for (int qq = 0; qq < APT; qq++) {
            int idx = qq*256 + tid;
            int row = idx / RQ, q = idx % RQ;
            const __nv_bfloat16* ap;
            if      (MODE == 0) ap = c_bf   + (size_t)(m0+row)*1024 + k0;
            else if (MODE == 1) ap = pos_bf + (size_t)(m0+row)*1024 + k0;
            else if (MODE == 2) ap = g_qu + ((size_t)bh*1024 + m0+row)*64 + k0;
            else if (MODE == 3) ap = g_qv + ((size_t)bh*1024 + m0+row)*64 + k0;
            else if (MODE == 4) ap = g_P  + ((size_t)bh*1024 + m0+row)*2048 + k0;
            else                ap = g_avec + (size_t)(m0+row)*1024 + k0;
            *(uint4*)(smem + row*SA + q*16) = *(const uint4*)(ap + q*8);
        }
        constexpr int BPT = NT*RQ/256;
#pragma unroll
        for (int qq = 0; qq < BPT; qq++) {
            int idx = qq*256 + tid;
            int row = idx / RQ, q = idx % RQ;
            const __nv_bfloat16* bp;
            if      (MODE == 0) bp = wqkvT + (size_t)(n0+row)*1024 + k0;
            else if (MODE == 1) bp = wrelT + (size_t)(n0+row)*1024 + k0;
            else if (MODE == 2) bp = g_k + ((size_t)bh*2048 + n0+row)*64 + k0;
            else if (MODE == 3) bp = g_r + ((size_t)h*2048 + n0+row)*64 + k0;
            else if (MODE == 4) bp = g_vT + ((size_t)bh*64 + row)*2048 + k0;
            else                bp = woT + (size_t)(n0+row)*1024 + k0;
            *(uint4*)(smB + row*SA + q*16) = *(const uint4*)(bp + q*8);
        }
        __syncthreads();
#pragma unroll
        for (int ks = 0; ks < KC/16; ks++) {
            const int colb = ks*32 + (lane >> 4)*16;
            uint32_t af[4][4];
#pragma unroll
            for (int mf = 0; mf < 4; mf++) {
                int r = wm*64 + mf*16 + (lane & 15);
                ldm_x4(af[mf], smA32 + r*SA + colb);
            }
            uint32_t bfr[NF][2];
#pragma unroll
            for (int nf2 = 0; nf2 < NF/2; nf2++) {
                uint32_t t4[4];
                int r = wn*(NT/4) + nf2*16 + (lane & 15);
                ldm_x4(t4, smB32 + r*SA + colb);
                bfr[2*nf2][0]   = t4[0]; bfr[2*nf2][1]   = t4[2];
                bfr[2*nf2+1][0] = t4[1]; bfr[2*nf2+1][1] = t4[3];
            }
#pragma unroll
            for (int mf = 0; mf < 4; mf++)
#pragma unroll
                for (int nf = 0; nf < NF; nf++)
                    mma16816(acc[mf][nf], af[mf], bfr[nf]);
        }
        __syncthreads();
    }

    // ---- dump fragments to staged SMEM [128][NT+1] ----
#pragma unroll
    for (int mf = 0; mf < 4; mf++)
#pragma unroll
        for (int nf = 0; nf < NF; nf++) {
            int r0 = wm*64 + mf*16 + (lane >> 2);
            int c0 = wn*(NT/4) + nf*8 + (lane & 3)*2;
            stage[r0*(NT+1)+c0]       = acc[mf][nf][0];
            stage[r0*(NT+1)+c0+1]     = acc[mf][nf][1];
            stage[(r0+8)*(NT+1)+c0]   = acc[mf][nf][2];
            stage[(r0+8)*(NT+1)+c0+1] = acc[mf][nf][3];
        }
    __syncthreads();
    if (tid >= 128) return;

#define STG(r,c) stage[(r)*(NT+1)+(c)]

    if (MODE == 0) {
#pragma unroll
        for (int g = 0; g < 4; g++) {
            const int gc0 = n0 + g*32;
            const int which = gc0 >> 10;
            const int hc0 = gc0 & 1023;
            const int hh = hc0 >> 6, dh0 = hc0 & 63;
            const int n = m0 + tid, t = n >> 2, bb = n & 3;
            if (which == 0) {
                if (t >= 1024) {
                    uint32_t pu[16], pv[16];
#pragma unroll
                    for (int c = 0; c < 32; c += 2) {
                        float v0 = STG(tid, g*32+c), v1 = STG(tid, g*32+c+1);
                        pu[c>>1] = pk2(v0 + bu[hc0+c], v1 + bu[hc0+c+1]);
                        pv[c>>1] = pk2(v0 + bv[hc0+c], v1 + bv[hc0+c+1]);
                    }
                    size_t base = ((size_t)(bb*16+hh)*1024 + (t-1024))*64 + dh0;
#pragma unroll
                    for (int q = 0; q < 4; q++) {
                        *(uint4*)(g_qu + base + q*8) = make_uint4(pu[q*4], pu[q*4+1], pu[q*4+2], pu[q*4+3]);
                        *(uint4*)(g_qv + base + q*8) = make_uint4(pv[q*4], pv[q*4+1], pv[q*4+2], pv[q*4+3]);
                    }
                }
            } else if (which == 1) {
                uint32_t pk[16];
#pragma unroll
                for (int c = 0; c < 32; c += 2) pk[c>>1] = pk2(STG(tid, g*32+c), STG(tid, g*32+c+1));
                size_t base = ((size_t)(bb*16+hh)*2048 + t)*64 + dh0;
#pragma unroll
                for (int q = 0; q < 4; q++)
                    *(uint4*)(g_k + base + q*8) = make_uint4(pk[q*4], pk[q*4+1], pk[q*4+2], pk[q*4+3]);
            } else {
                const int c2 = tid & 31, sub = tid >> 5;
                const int t0 = m0 >> 2;
                uint32_t w[16];
#pragma unroll
                for (int tl = 0; tl < 32; tl += 2)
                    w[tl>>1] = pk2(STG(tl*4+sub, g*32+c2), STG((tl+1)*4+sub, g*32+c2));
                size_t base = ((size_t)(sub*16+hh)*64 + dh0 + c2)*2048 + t0;
#pragma unroll
                for (int q = 0; q < 4; q++)
                    *(uint4*)(g_vT + base + q*8) = make_uint4(w[q*4], w[q*4+1], w[q*4+2], w[q*4+3]);
            }
        }
    } else if (MODE == 1) {
#pragma unroll
        for (int g = 0; g < 4; g++) {
            const int gc0 = n0 + g*32;
            const int hh = gc0 >> 6, dh0 = gc0 & 63;
            uint32_t pk[16];
#pragma unroll
            for (int c = 0; c < 32; c += 2) pk[c>>1] = pk2(STG(tid, g*32+c), STG(tid, g*32+c+1));
            size_t base = ((size_t)hh*2048 + (m0+tid))*64 + dh0;
#pragma unroll
            for (int q = 0; q < 4; q++)
                *(uint4*)(g_r + base + q*8) = make_uint4(pk[q*4], pk[q*4+1], pk[q*4+2], pk[q*4+3]);
        }
    } else if (MODE == 2) {
        const int i = m0 + tid;
        const float* bdrow = g_BD + ((size_t)bh*1024 + i)*2048 + (1023 - i);
        float* dst = g_AC + ((size_t)bh*1024 + i)*2048;
#pragma unroll
        for (int g = 0; g < 4; g++) {
            const int gc0 = n0 + g*32;
            float buf[32];
#pragma unroll
            for (int c = 0; c < 32; c++) {
                int j = gc0 + c;
                float s = 0.f;
                if (j <= i + 1024) s = (STG(tid, g*32+c) + bdrow[j]) * 0.125f;
                buf[c] = s;
            }
#pragma unroll
            for (int c = 0; c < 32; c += 4)
                *(float4*)(dst + gc0 + c) = make_float4(buf[c], buf[c+1], buf[c+2], buf[c+3]);
        }
    } else if (MODE == 3) {
        float* dst = g_BD + ((size_t)bh*1024 + m0+tid)*2048;
#pragma unroll
        for (int g = 0; g < 4; g++) {
            const int gc0 = n0 + g*32;
#pragma unroll
            for (int c = 0; c < 32; c += 4)
                *(float4*)(dst + gc0 + c) = make_float4(STG(tid, g*32+c),   STG(tid, g*32+c+1),
                                                        STG(tid, g*32+c+2), STG(tid, g*32+c+3));
        }
    } else if (MODE == 4) {
#pragma unroll
        for (int g = 0; g < 2; g++) {
            const int dh0 = g*32;
            uint32_t pk[16];
#pragma unroll
            for (int c = 0; c < 32; c += 2) pk[c>>1] = pk2(STG(tid, g*32+c), STG(tid, g*32+c+1));
            size_t base = ((size_t)(m0+tid)*4 + b)*1024 + h*64 + dh0;
#pragma unroll
            for (int q = 0; q < 4; q++)
                *(uint4*)(g_avec + base + q*8) = make_uint4(pk[q*4], pk[q*4+1], pk[q*4+2], pk[q*4+3]);
        }
    } else {
        float* dst = g_aout + (size_t)(m0+tid)*1024;
#pragma unroll
        for (int g = 0; g < 4; g++) {
            const int gc0 = n0 + g*32;
#pragma unroll
            for (int c = 0; c < 32; c += 4)
                *(float4*)(dst + gc0 + c) = make_float4(STG(tid, g*32+c),   STG(tid, g*32+c+1),
                                                        STG(tid, g*32+c+2), STG(tid, g*32+c+3));
        }
    }
#undef STG
}

// ---------------- softmax: logits already (AC + shifted BD)*scale in g_AC --------
__global__ void __launch_bounds__(256) softmax2()
{
    __shared__ float sh[8];
    const int i = blockIdx.x, bh = blockIdx.y;
    const float* ac = g_AC + ((size_t)bh*1024 + i)*2048;
    const int jmax = i + 1024;
    const int jlim = min(2048, (i & ~127) + 1152);   // PV reads only j < (m0 + 1152)
    const int tid = threadIdx.x;

    float sv[8];
    float m = -1e30f;
#pragma unroll
    for (int t = 0; t < 8; t++) {
        int j = tid + t*256;
        float s = (j <= jmax) ? ac[j] : -1e30f;
        sv[t] = s;
        m = fmaxf(m, s);
    }
#pragma unroll
    for (int o = 16; o > 0; o >>= 1) m = fmaxf(m, __shfl_xor_sync(0xffffffffu, m, o));
    if ((tid & 31) == 0) sh[tid >> 5] = m;
    __syncthreads();
    if (tid < 8) {
        float t = sh[tid];
#pragma unroll
        for (int o = 4; o > 0; o >>= 1) t = fmaxf(t, __shfl_xor_sync(0xffu, t, o));
        if (tid == 0) sh[0] = t;
    }
    __syncthreads();
    m = sh[0];
    __syncthreads();

    float sum = 0.f;
#pragma unroll
    for (int t = 0; t < 8; t++) { float e = expf(sv[t] - m); sv[t] = e; sum += e; }
#pragma unroll
    for (int o = 16; o > 0; o >>= 1) sum += __shfl_xor_sync(0xffffffffu, sum, o);
    if ((tid & 31) == 0) sh[tid >> 5] = sum;
    __syncthreads();
    if (tid < 8) {
        float t = sh[tid];
#pragma unroll
        for (int o = 4; o > 0; o >>= 1) t += __shfl_xor_sync(0xffu, t, o);
        if (tid == 0) sh[0] = t;
    }
    __syncthreads();
    const float inv = 1.0f / sh[0];

    __nv_bfloat16* dst = g_P + ((size_t)bh*1024 + i)*2048;
#pragma unroll
    for (int t = 0; t < 8; t++) {
        int j = tid + t*256;
        if (j < jlim) dst[j] = __float2bfloat16(sv[t] * inv);
    }
}

// ---------------- residual + LayerNorm ------------------------------------------
__global__ void __launch_bounds__(256) ln_kernel(
    const float* __restrict__ x, const float* __restrict__ gamma,
    const float* __restrict__ beta, float* __restrict__ out)
{
    __shared__ float shs[8], shss[8];
    const int n = blockIdx.x;
    const int tid = threadIdx.x;
    const float* xr = x + (size_t)n * DMODEL;
    const float* ar = g_aout + (size_t)n * DMODEL;

    float vals[4];
    float s = 0.f, ss = 0.f;
#pragma unroll
    for (int q = 0; q < 4; q++) {
        int d = tid + q*256;
        float y = xr[d] + ar[d];
        vals[q] = y; s += y; ss += y*y;
    }
#pragma unroll
    for (int o = 16; o > 0; o >>= 1) {
        s  += __shfl_xor_sync(0xffffffffu, s, o);
        ss += __shfl_xor_sync(0xffffffffu, ss, o);
    }
    if ((tid & 31) == 0) { shs[tid>>5] = s; shss[tid>>5] = ss; }
    __syncthreads();
    if (tid < 8) {
        float t1 = shs[tid], t2 = shss[tid];
#pragma unroll
        for (int o = 4; o > 0; o >>= 1) {
            t1 += __shfl_xor_sync(0xffu, t1, o);
            t2 += __shfl_xor_sync(0xffu, t2, o);
        }
        if (tid == 0) { shs[0] = t1; shss[0] = t2; }
    }
    __syncthreads();
    const float mu = shs[0] * (1.0f/DMODEL);
    const float var = shss[0] * (1.0f/DMODEL) - mu*mu;
    const float inv = rsqrtf(var + 1e-5f);

    float* orow = out + (size_t)n * DMODEL;
#pragma unroll
    for (int q = 0; q < 4; q++) {
        int d = tid + q*256;
        orow[d] = (vals[q] - mu) * inv * gamma[d] + beta[d];
    }
}

// ---------------- launch ---------------------------------------------------------
extern "C" void kernel_launch(void* const* d_in, const int* in_sizes, int n_in,
                              void* d_out, int out_size)
{
    (void)in_sizes; (void)n_in; (void)out_size;
    const float* x       = (const float*)d_in[0];
    const float* pos_emb = (const float*)d_in[1];
    const float* bu      = (const float*)d_in[2];
    const float* bv      = (const float*)d_in[3];
    const float* memory  = (const float*)d_in[4];
    const float* W_qkv   = (const float*)d_in[5];
    const float* W_rel   = (const float*)d_in[6];
    const float* W_o     = (const float*)d_in[7];
    const float* gamma   = (const float*)d_in[8];
    const float* beta    = (const float*)d_in[9];
    float* out = (float*)d_out;

    // smem sizes: A + B tiles (padded) + fp32 stage [128][NT+1]
    const int SM_BIG = 128*272 + 128*272 + 128*129*4;  // 135680 (modes 0,1,5)
    const int SM_AB  = 128*144 + 128*144 + 128*129*4;  // 102912 (modes 2,3)
    const int SM_PV  = 128*272 +  64*272 + 128*65*4;   //  85504 (mode 4)

    cudaFuncSetAttribute(gemm_tc<0>, cudaFuncAttributeMaxDynamicSharedMemorySize, SM_BIG);
    cudaFuncSetAttribute(gemm_tc<1>, cudaFuncAttributeMaxDynamicSharedMemorySize, SM_BIG);
    cudaFuncSetAttribute(gemm_tc<2>, cudaFuncAttributeMaxDynamicSharedMemorySize, SM_AB);
    cudaFuncSetAttribute(gemm_tc<3>, cudaFuncAttributeMaxDynamicSharedMemorySize, SM_AB);
    cudaFuncSetAttribute(gemm_tc<4>, cudaFuncAttributeMaxDynamicSharedMemorySize, SM_PV);
    cudaFuncSetAttribute(gemm_tc<5>, cudaFuncAttributeMaxDynamicSharedMemorySize, SM_BIG);

    conv_c<<<8192, 256>>>(memory, x);
    conv_pos<<<2048, 256>>>(pos_emb);
    transpose_bf<<<dim3(96, 32), 256>>>(W_qkv, 0, 3072);
    transpose_bf<<<dim3(32, 32), 256>>>(W_rel, 1, 1024);
    transpose_bf<<<dim3(32, 32), 256>>>(W_o,   2, 1024);

    gemm_tc<0><<<dim3(24, 64),    256, SM_BIG>>>(bu, bv);            // QKV
    gemm_tc<1><<<dim3(8, 16),     256, SM_BIG>>>(nullptr, nullptr);  // REL
    gemm_tc<3><<<dim3(16, 8, 64), 256, SM_AB>>>(nullptr, nullptr);   // BD (first)
    gemm_tc<2><<<dim3(16, 8, 64), 256, SM_AB>>>(nullptr, nullptr);   // AC + shifted BD -> logits
    softmax2<<<dim3(1024, 64), 256>>>();
    gemm_tc<4><<<dim3(1, 8, 64),  256, SM_PV>>>(nullptr, nullptr);   // PV
    gemm_tc<5><<<dim3(8, 32),     256, SM_BIG>>>(nullptr, nullptr);  // OUT
    ln_kernel<<<4096, 256>>>(x, gamma, beta, out);
}

// round 10
// speedup vs baseline: 3.7319x; 1.5988x over previous
#include <cuda_runtime.h>
#include <cuda_bf16.h>
#include <math.h>
#include <stdint.h>

#define SQ 1024
#define DMODEL 1024

// ---------------- scratch (static device globals; allocation-free) -------------
__device__ __nv_bfloat16 c_bf  [(size_t)8192*1024];   // concat(memory,x), row n=t*4+b
__device__ __nv_bfloat16 pos_bf[(size_t)2048*1024];
__device__ __nv_bfloat16 wqkvT [(size_t)3072*1024];   // W_qkv^T
__device__ __nv_bfloat16 wrelT [(size_t)1024*1024];
__device__ __nv_bfloat16 woT   [(size_t)1024*1024];
__device__ __nv_bfloat16 g_qu  [(size_t)64*1024*64];  // [bh][i][dh]
__device__ __nv_bfloat16 g_qv  [(size_t)64*1024*64];
__device__ __nv_bfloat16 g_k   [(size_t)64*2048*64];  // [bh][t][dh]
__device__ __nv_bfloat16 g_vT  [(size_t)64*64*2048];  // [bh][dh][t]
__device__ __nv_bfloat16 g_r   [(size_t)16*2048*64];  // [h][p][dh]
__device__ __nv_bfloat16 g_BDs [(size_t)64*1024*2048];// pre-SHIFTED BD, [bh][i][j] bf16, 256MB
__device__ __nv_bfloat16 g_avec[(size_t)4096*1024];   // [i*4+b][h*64+dh]
__device__ float         g_aout[(size_t)4096*1024];

// ---------------- helpers -------------------------------------------------------
__device__ __forceinline__ uint32_t smem_u32(const void* p){
    uint32_t a;
    asm("{ .reg .u64 t; cvta.to.shared.u64 t, %1; cvt.u32.u64 %0, t; }" : "=r"(a) : "l"(p));
    return a;
}
__device__ __forceinline__ uint32_t pk2(float a, float b){
    return (uint32_t)__bfloat16_as_ushort(__float2bfloat16(a))
         | ((uint32_t)__bfloat16_as_ushort(__float2bfloat16(b)) << 16);
}
__device__ __forceinline__ float lo_bf(uint32_t u){
    return __bfloat162float(__ushort_as_bfloat16((unsigned short)(u & 0xffffu)));
}
__device__ __forceinline__ float hi_bf(uint32_t u){
    return __bfloat162float(__ushort_as_bfloat16((unsigned short)(u >> 16)));
}
__device__ __forceinline__ void ldm_x4(uint32_t* r, uint32_t addr){
    asm volatile("ldmatrix.sync.aligned.m8n8.x4.shared.b16 {%0,%1,%2,%3}, [%4];"
        : "=r"(r[0]), "=r"(r[1]), "=r"(r[2]), "=r"(r[3]) : "r"(addr));
}
__device__ __forceinline__ void mma16816(float* c, const uint32_t* a, const uint32_t* b){
    asm volatile("mma.sync.aligned.m16n8k16.row.col.f32.bf16.bf16.f32 "
        "{%0,%1,%2,%3}, {%4,%5,%6,%7}, {%8,%9}, {%0,%1,%2,%3};"
        : "+f"(c[0]), "+f"(c[1]), "+f"(c[2]), "+f"(c[3])
        : "r"(a[0]), "r"(a[1]), "r"(a[2]), "r"(a[3]), "r"(b[0]), "r"(b[1]));
}

// ---------------- prep kernels --------------------------------------------------
__global__ void __launch_bounds__(256) conv_c(const float* __restrict__ mem, const float* __restrict__ x){
    size_t n = blockIdx.x;
    const float* src = (n < 4096) ? (mem + n*1024) : (x + (n-4096)*1024);
    __nv_bfloat16* dst = c_bf + n*1024;
#pragma unroll
    for (int q = 0; q < 4; q++){ int d = threadIdx.x + q*256; dst[d] = __float2bfloat16(src[d]); }
}
__global__ void __launch_bounds__(256) conv_pos(const float* __restrict__ pe){
    size_t n = blockIdx.x;
    const float* src = pe + n*1024;
    __nv_bfloat16* dst = pos_bf + n*1024;
#pragma unroll
    for (int q = 0; q < 4; q++){ int d = threadIdx.x + q*256; dst[d] = __float2bfloat16(src[d]); }
}
// transpose fp32 [1024][C] -> bf16 [C][1024]
__global__ void __launch_bounds__(256) transpose_bf(const float* __restrict__ src, int mode, int C){
    __shared__ float tile[32][33];
    __nv_bfloat16* dst = (mode == 0) ? wqkvT : (mode == 1) ? wrelT : woT;
    const int R = 1024;
    int c0 = blockIdx.x*32, r0 = blockIdx.y*32;
    int tx = threadIdx.x & 31, ty = threadIdx.x >> 5;
#pragma unroll
    for (int q = 0; q < 4; q++)
        tile[ty + q*8][tx] = src[(size_t)(r0 + ty + q*8)*C + c0 + tx];
    __syncthreads();
#pragma unroll
    for (int q = 0; q < 4; q++)
        dst[(size_t)(c0 + ty + q*8)*R + r0 + tx] = __float2bfloat16(tile[tx][ty + q*8]);
}

// ---------------- generic mma.sync GEMM (modes 0,1,3,5) --------------------------
// MODE 0: QKV   c_bf(8192x1024) @ wqkvT^T  -> scatter qu/qv/k/vT (bf16)
// MODE 1: REL   pos_bf(2048x1024) @ wrelT^T -> g_r (bf16)
// MODE 3: BD    qv(1024x64) @ r^T(2048x64) per bh -> pre-shifted bf16 g_BDs
// MODE 5: OUT   avec(4096x1024) @ woT^T   -> g_aout (f32)
template<int MODE>
__global__ void __launch_bounds__(256) gemm_tc(const float* __restrict__ bu, const float* __restrict__ bv)
{
    constexpr int KC = (MODE == 3) ? 64 : 128;
    constexpr int NT = 128;
    constexpr int NF = NT / 32;
    constexpr int SA = KC*2 + 16;
    constexpr int ASZ = 128*SA;
    constexpr int BSZ = NT*SA;
    extern __shared__ char smem[];
    char* smB = smem + ASZ;
    float* stage = (float*)(smem + ASZ + BSZ);   // [128][NT+1]
    const uint32_t smA32 = smem_u32(smem);
    const uint32_t smB32 = smA32 + ASZ;

    const int tid = threadIdx.x;
    const int lane = tid & 31, wid = tid >> 5;
    const int wm = wid & 1, wn = wid >> 1;

    int m0, n0, bh = 0, h = 0, nchunks;
    if (MODE == 0)      { m0 = blockIdx.y*128; n0 = blockIdx.x*128; nchunks = 8; }
    else if (MODE == 1) { m0 = blockIdx.y*128; n0 = blockIdx.x*128; nchunks = 8; }
    else if (MODE == 3) { bh = blockIdx.z; h = bh & 15; m0 = blockIdx.y*128; n0 = blockIdx.x*128;
                          if (n0 + m0 <= 768) return; nchunks = 1; }
    else                { m0 = blockIdx.y*128; n0 = blockIdx.x*128; nchunks = 8; }

    float acc[4][NF][4] = {};

    for (int ch = 0; ch < nchunks; ch++) {
        const int k0 = ch * KC;
        constexpr int RQ = KC/8;
        constexpr int APT = 128*RQ/256;
#pragma unroll
        for (int qq = 0; qq < APT; qq++) {
            int idx = qq*256 + tid;
            int row = idx / RQ, q = idx % RQ;
            const __nv_bfloat16* ap;
            if      (MODE == 0) ap = c_bf   + (size_t)(m0+row)*1024 + k0;
            else if (MODE == 1) ap = pos_bf + (size_t)(m0+row)*1024 + k0;
            else if (MODE == 3) ap = g_qv + ((size_t)bh*1024 + m0+row)*64 + k0;
            else                ap = g_avec + (size_t)(m0+row)*1024 + k0;
            *(uint4*)(smem + row*SA + q*16) = *(const uint4*)(ap + q*8);
        }
        constexpr int BPT = NT*RQ/256;
#pragma unroll
        for (int qq = 0; qq < BPT; qq++) {
            int idx = qq*256 + tid;
            int row = idx / RQ, q = idx % RQ;
            const __nv_bfloat16* bp;
            if      (MODE == 0) bp = wqkvT + (size_t)(n0+row)*1024 + k0;
            else if (MODE == 1) bp = wrelT + (size_t)(n0+row)*1024 + k0;
            else if (MODE == 3) bp = g_r + ((size_t)h*2048 + n0+row)*64 + k0;
            else                bp = woT + (size_t)(n0+row)*1024 + k0;
            *(uint4*)(smB + row*SA + q*16) = *(const uint4*)(bp + q*8);
        }
        __syncthreads();
#pragma unroll
        for (int ks = 0; ks < KC/16; ks++) {
            const int colb = ks*32 + (lane >> 4)*16;
            uint32_t af[4][4];
#pragma unroll
            for (int mf = 0; mf < 4; mf++) {
                int r = wm*64 + mf*16 + (lane & 15);
                ldm_x4(af[mf], smA32 + r*SA + colb);
            }
            uint32_t bfr[NF][2];
#pragma unroll
            for (int nf2 = 0; nf2 < NF/2; nf2++) {
                uint32_t t4[4];
                int r = wn*(NT/4) + nf2*16 + (lane & 15);
                ldm_x4(t4, smB32 + r*SA + colb);
                bfr[2*nf2][0]   = t4[0]; bfr[2*nf2][1]   = t4[2];
                bfr[2*nf2+1][0] = t4[1]; bfr[2*nf2+1][1] = t4[3];
            }
#pragma unroll
            for (int mf = 0; mf < 4; mf++)
#pragma unroll
                for (int nf = 0; nf < NF; nf++)
                    mma16816(acc[mf][nf], af[mf], bfr[nf]);
        }
        __syncthreads();
    }

    // ---- dump fragments to staged SMEM [128][NT+1] ----
#pragma unroll
    for (int mf = 0; mf < 4; mf++)
#pragma unroll
        for (int nf = 0; nf < NF; nf++) {
            int r0 = wm*64 + mf*16 + (lane >> 2);
            int c0 = wn*(NT/4) + nf*8 + (lane & 3)*2;
            stage[r0*(NT+1)+c0]       = acc[mf][nf][0];
            stage[r0*(NT+1)+c0+1]     = acc[mf][nf][1];
            stage[(r0+8)*(NT+1)+c0]   = acc[mf][nf][2];
            stage[(r0+8)*(NT+1)+c0+1] = acc[mf][nf][3];
        }
    __syncthreads();
    if (tid >= 128) return;

#define STG(r,c) stage[(r)*(NT+1)+(c)]

    if (MODE == 0) {
#pragma unroll
        for (int g = 0; g < 4; g++) {
            const int gc0 = n0 + g*32;
            const int which = gc0 >> 10;
            const int hc0 = gc0 & 1023;
            const int hh = hc0 >> 6, dh0 = hc0 & 63;
            const int n = m0 + tid, t = n >> 2, bb = n & 3;
            if (which == 0) {
                if (t >= 1024) {
                    uint32_t pu[16], pv[16];
#pragma unroll
                    for (int c = 0; c < 32; c += 2) {
                        float v0 = STG(tid, g*32+c), v1 = STG(tid, g*32+c+1);
                        pu[c>>1] = pk2(v0 + bu[hc0+c], v1 + bu[hc0+c+1]);
                        pv[c>>1] = pk2(v0 + bv[hc0+c], v1 + bv[hc0+c+1]);
                    }
                    size_t base = ((size_t)(bb*16+hh)*1024 + (t-1024))*64 + dh0;
#pragma unroll
                    for (int q = 0; q < 4; q++) {
                        *(uint4*)(g_qu + base + q*8) = make_uint4(pu[q*4], pu[q*4+1], pu[q*4+2], pu[q*4+3]);
                        *(uint4*)(g_qv + base + q*8) = make_uint4(pv[q*4], pv[q*4+1], pv[q*4+2], pv[q*4+3]);
                    }
                }
            } else if (which == 1) {
                uint32_t pk[16];
#pragma unroll
                for (int c = 0; c < 32; c += 2) pk[c>>1] = pk2(STG(tid, g*32+c), STG(tid, g*32+c+1));
                size_t base = ((size_t)(bb*16+hh)*2048 + t)*64 + dh0;
#pragma unroll
                for (int q = 0; q < 4; q++)
                    *(uint4*)(g_k + base + q*8) = make_uint4(pk[q*4], pk[q*4+1], pk[q*4+2], pk[q*4+3]);
            } else {
                const int c2 = tid & 31, sub = tid >> 5;
                const int t0 = m0 >> 2;
                uint32_t w[16];
#pragma unroll
                for (int tl = 0; tl < 32; tl += 2)
                    w[tl>>1] = pk2(STG(tl*4+sub, g*32+c2), STG((tl+1)*4+sub, g*32+c2));
                size_t base = ((size_t)(sub*16+hh)*64 + dh0 + c2)*2048 + t0;
#pragma unroll
                for (int q = 0; q < 4; q++)
                    *(uint4*)(g_vT + base + q*8) = make_uint4(w[q*4], w[q*4+1], w[q*4+2], w[q*4+3]);
            }
        }
    } else if (MODE == 1) {
#pragma unroll
        for (int g = 0; g < 4; g++) {
            const int gc0 = n0 + g*32;
            const int hh = gc0 >> 6, dh0 = gc0 & 63;
            uint32_t pk[16];
#pragma unroll
            for (int c = 0; c < 32; c += 2) pk[c>>1] = pk2(STG(tid, g*32+c), STG(tid, g*32+c+1));
            size_t base = ((size_t)hh*2048 + (m0+tid))*64 + dh0;
#pragma unroll
            for (int q = 0; q < 4; q++)
                *(uint4*)(g_r + base + q*8) = make_uint4(pk[q*4], pk[q*4+1], pk[q*4+2], pk[q*4+3]);
        }
    } else if (MODE == 3) {
        // pre-shifted BD store: g_BDs[bh][i][j] = BD[i][p], j = p + i - 1023
        const int i = m0 + tid;
        __nv_bfloat16* dst = g_BDs + ((size_t)bh*1024 + i)*2048;
#pragma unroll
        for (int g = 0; g < 4; g++) {
            const int gc0 = n0 + g*32;
            const int jbase = gc0 + i - 1023;
            float v[32];
#pragma unroll
            for (int c = 0; c < 32; c++) v[c] = STG(tid, g*32+c);
            if (!(jbase & 1)) {
#pragma unroll
                for (int c = 0; c < 32; c += 2) {
                    int j = jbase + c;
                    if (j >= 0) *(uint32_t*)(dst + j) = pk2(v[c], v[c+1]);
                }
            } else {
                if (jbase >= 0) dst[jbase] = __float2bfloat16(v[0]);
#pragma unroll
                for (int c = 1; c < 31; c += 2) {
                    int j = jbase + c;
                    if (j >= 0) *(uint32_t*)(dst + j) = pk2(v[c], v[c+1]);
                }
                if (jbase + 31 >= 0) dst[jbase + 31] = __float2bfloat16(v[31]);
            }
        }
    } else {
        float* dst = g_aout + (size_t)(m0+tid)*1024;
#pragma unroll
        for (int g = 0; g < 4; g++) {
            const int gc0 = n0 + g*32;
#pragma unroll
            for (int c = 0; c < 32; c += 4)
                *(float4*)(dst + gc0 + c) = make_float4(STG(tid, g*32+c),   STG(tid, g*32+c+1),
                                                        STG(tid, g*32+c+2), STG(tid, g*32+c+3));
        }
    }
#undef STG
}

// ---------------- fused flash attention: S = qu*K^T + BDshift, softmax, O = P*V --
// grid (8 i-tiles, 64 bh), 256 threads. Warp w owns query rows [16w, 16w+16).
__global__ void __launch_bounds__(256, 1) flash_attn()
{
    __shared__ __align__(16) char smK[128*144];   // K tile [128 j][64 k], also qu tile at start
    __shared__ __align__(16) char smV[64*272];    // VT tile [64 dh][128 j]
    const uint32_t smK32 = smem_u32(smK);
    const uint32_t smV32 = smem_u32(smV);

    const int bh = blockIdx.y, b = bh >> 4, h = bh & 15;
    const int m0 = (7 - blockIdx.x) * 128;        // longest-work-first
    const int tid = threadIdx.x, lane = tid & 31, w = tid >> 5;
    const int r0 = w * 16;

    // ---- qu tile -> smem -> A fragments (held in regs for all j-tiles) ----
    {
        const __nv_bfloat16* qp = g_qu + ((size_t)bh*1024 + m0)*64;
#pragma unroll
        for (int q4 = 0; q4 < 4; q4++) {
            int idx = q4*256 + tid; int row = idx >> 3, q = idx & 7;
            *(uint4*)(smK + row*144 + q*16) = *(const uint4*)(qp + (size_t)row*64 + q*8);
        }
    }
    __syncthreads();
    uint32_t af[4][4];
#pragma unroll
    for (int ks = 0; ks < 4; ks++)
        ldm_x4(af[ks], smK32 + (r0 + (lane & 15))*144 + ks*32 + (lane >> 4)*16);
    __syncthreads();

    float mrow0 = -1e30f, mrow1 = -1e30f, lrow0 = 0.f, lrow1 = 0.f;
    float oacc[8][4] = {};
    const int ia = m0 + r0 + (lane >> 2);         // row A; row B = ia + 8
    const uint32_t* bdr0 = (const uint32_t*)(g_BDs + ((size_t)bh*1024 + ia)*2048);
    const uint32_t* bdr1 = (const uint32_t*)(g_BDs + ((size_t)bh*1024 + ia + 8)*2048);

    const int ntiles = m0/128 + 9;
    for (int jt = 0; jt < ntiles; jt++) {
        const int j0 = jt * 128;
        {
            const __nv_bfloat16* kp = g_k + ((size_t)bh*2048 + j0)*64;
#pragma unroll
            for (int q4 = 0; q4 < 4; q4++) {
                int idx = q4*256 + tid; int row = idx >> 3, q = idx & 7;
                *(uint4*)(smK + row*144 + q*16) = *(const uint4*)(kp + (size_t)row*64 + q*8);
            }
            const __nv_bfloat16* vp = g_vT + ((size_t)bh*64)*2048 + j0;
#pragma unroll
            for (int q4 = 0; q4 < 4; q4++) {
                int idx = q4*256 + tid; int row = idx >> 4, q = idx & 15;
                *(uint4*)(smV + row*272 + q*16) = *(const uint4*)(vp + (size_t)row*2048 + q*8);
            }
        }
        __syncthreads();

        // ---- S = qu * K^T  (16 rows x 128 cols per warp) ----
        float sacc[16][4] = {};
#pragma unroll
        for (int ks = 0; ks < 4; ks++) {
            uint32_t bfrg[16][2];
#pragma unroll
            for (int nb = 0; nb < 8; nb++) {
                uint32_t t4[4];
                ldm_x4(t4, smK32 + (nb*16 + (lane & 15))*144 + ks*32 + (lane >> 4)*16);
                bfrg[2*nb][0]   = t4[0]; bfrg[2*nb][1]   = t4[2];
                bfrg[2*nb+1][0] = t4[1]; bfrg[2*nb+1][1] = t4[3];
            }
#pragma unroll
            for (int nf = 0; nf < 16; nf++) mma16816(sacc[nf], af[ks], bfrg[nf]);
        }

        // ---- logits: + shifted BD, * scale, causal mask (predicated select) ----
        float tmax0 = -1e30f, tmax1 = -1e30f;
#pragma unroll
        for (int nf = 0; nf < 16; nf++) {
            int j = j0 + nf*8 + (lane & 3)*2;
            uint32_t bdA = bdr0[j >> 1];
            uint32_t bdB = bdr1[j >> 1];
            float a0 = (sacc[nf][0] + lo_bf(bdA)) * 0.125f;
            float a1 = (sacc[nf][1] + hi_bf(bdA)) * 0.125f;
            float b0 = (sacc[nf][2] + lo_bf(bdB)) * 0.125f;
            float b1 = (sacc[nf][3] + hi_bf(bdB)) * 0.125f;
            sacc[nf][0] = (j     <= ia + 1024)     ? a0 : -1e30f;
            sacc[nf][1] = (j + 1 <= ia + 1024)     ? a1 : -1e30f;
            sacc[nf][2] = (j     <= ia + 8 + 1024) ? b0 : -1e30f;
            sacc[nf][3] = (j + 1 <= ia + 8 + 1024) ? b1 : -1e30f;
            tmax0 = fmaxf(tmax0, fmaxf(sacc[nf][0], sacc[nf][1]));
            tmax1 = fmaxf(tmax1, fmaxf(sacc[nf][2], sacc[nf][3]));
        }
        tmax0 = fmaxf(tmax0, __shfl_xor_sync(0xffffffffu, tmax0, 1));
        tmax0 = fmaxf(tmax0, __shfl_xor_sync(0xffffffffu, tmax0, 2));
        tmax1 = fmaxf(tmax1, __shfl_xor_sync(0xffffffffu, tmax1, 1));
        tmax1 = fmaxf(tmax1, __shfl_xor_sync(0xffffffffu, tmax1, 2));

        const float mnew0 = fmaxf(mrow0, tmax0), mnew1 = fmaxf(mrow1, tmax1);
        const float f0 = __expf(mrow0 - mnew0), f1 = __expf(mrow1 - mnew1);
        mrow0 = mnew0; mrow1 = mnew1;
        lrow0 *= f0; lrow1 *= f1;
#pragma unroll
        for (int nf = 0; nf < 8; nf++) {
            oacc[nf][0] *= f0; oacc[nf][1] *= f0;
            oacc[nf][2] *= f1; oacc[nf][3] *= f1;
        }

        // ---- P = exp(S - m), pack acc frags -> A frags ----
        uint32_t pf[8][4];
        float s0 = 0.f, s1 = 0.f;
#pragma unroll
        for (int kf = 0; kf < 8; kf++) {
            float e00 = __expf(sacc[2*kf][0]   - mnew0), e01 = __expf(sacc[2*kf][1]   - mnew0);
            float e02 = __expf(sacc[2*kf][2]   - mnew1), e03 = __expf(sacc[2*kf][3]   - mnew1);
            float e10 = __expf(sacc[2*kf+1][0] - mnew0), e11 = __expf(sacc[2*kf+1][1] - mnew0);
            float e12 = __expf(sacc[2*kf+1][2] - mnew1), e13 = __expf(sacc[2*kf+1][3] - mnew1);
            s0 += e00 + e01 + e10 + e11;
            s1 += e02 + e03 + e12 + e13;
            pf[kf][0] = pk2(e00, e01);
            pf[kf][1] = pk2(e02, e03);
            pf[kf][2] = pk2(e10, e11);
            pf[kf][3] = pk2(e12, e13);
        }
        lrow0 += s0; lrow1 += s1;

        // ---- O += P * V ----
#pragma unroll
        for (int kf = 0; kf < 8; kf++) {
            uint32_t bv[8][2];
#pragma unroll
            for (int nb = 0; nb < 4; nb++) {
                uint32_t t4[4];
                ldm_x4(t4, smV32 + (nb*16 + (lane & 15))*272 + kf*32 + (lane >> 4)*16);
                bv[2*nb][0]   = t4[0]; bv[2*nb][1]   = t4[2];
                bv[2*nb+1][0] = t4[1]; bv[2*nb+1][1] = t4[3];
            }
#pragma unroll
            for (int nf = 0; nf < 8; nf++) mma16816(oacc[nf], pf[kf], bv[nf]);
        }
        __syncthreads();
    }

    // ---- finalize: O /= l, write bf16 to g_avec ----
    lrow0 += __shfl_xor_sync(0xffffffffu, lrow0, 1);
    lrow0 += __shfl_xor_sync(0xffffffffu, lrow0, 2);
    lrow1 += __shfl_xor_sync(0xffffffffu, lrow1, 1);
    lrow1 += __shfl_xor_sync(0xffffffffu, lrow1, 2);
    const float inv0 = 1.f / lrow0, inv1 = 1.f / lrow1;

    __nv_bfloat16* d0 = g_avec + ((size_t)ia*4 + b)*1024 + h*64;
    __nv_bfloat16* d1 = g_avec + ((size_t)(ia+8)*4 + b)*1024 + h*64;
#pragma unroll
    for (int nf = 0; nf < 8; nf++) {
        int c = nf*8 + (lane & 3)*2;
        *(uint32_t*)(d0 + c) = pk2(oacc[nf][0]*inv0, oacc[nf][1]*inv0);
        *(uint32_t*)(d1 + c) = pk2(oacc[nf][2]*inv1, oacc[nf][3]*inv1);
    }
}

// ---------------- residual + LayerNorm ------------------------------------------
__global__ void __launch_bounds__(256) ln_kernel(
    const float* __restrict__ x, const float* __restrict__ gamma,
    const float* __restrict__ beta, float* __restrict__ out)
{
    __shared__ float shs[8], shss[8];
    const int n = blockIdx.x;
    const int tid = threadIdx.x;
    const float* xr = x + (size_t)n * DMODEL;
    const float* ar = g_aout + (size_t)n * DMODEL;

    float vals[4];
    float s = 0.f, ss = 0.f;
#pragma unroll
    for (int q = 0; q < 4; q++) {
        int d = tid + q*256;
        float y = xr[d] + ar[d];
        vals[q] = y; s += y; ss += y*y;
    }
#pragma unroll
    for (int o = 16; o > 0; o >>= 1) {
        s  += __shfl_xor_sync(0xffffffffu, s, o);
        ss += __shfl_xor_sync(0xffffffffu, ss, o);
    }
    if ((tid & 31) == 0) { shs[tid>>5] = s; shss[tid>>5] = ss; }
    __syncthreads();
    if (tid < 8) {
        float t1 = shs[tid], t2 = shss[tid];
#pragma unroll
        for (int o = 4; o > 0; o >>= 1) {
            t1 += __shfl_xor_sync(0xffu, t1, o);
            t2 += __shfl_xor_sync(0xffu, t2, o);
        }
        if (tid == 0) { shs[0] = t1; shss[0] = t2; }
    }
    __syncthreads();
    const float mu = shs[0] * (1.0f/DMODEL);
    const float var = shss[0] * (1.0f/DMODEL) - mu*mu;
    const float inv = rsqrtf(var + 1e-5f);

    float* orow = out + (size_t)n * DMODEL;
#pragma unroll
    for (int q = 0; q < 4; q++) {
        int d = tid + q*256;
        orow[d] = (vals[q] - mu) * inv * gamma[d] + beta[d];
    }
}

// ---------------- launch ---------------------------------------------------------
extern "C" void kernel_launch(void* const* d_in, const int* in_sizes, int n_in,
                              void* d_out, int out_size)
{
    (void)in_sizes; (void)n_in; (void)out_size;
    const float* x       = (const float*)d_in[0];
    const float* pos_emb = (const float*)d_in[1];
    const float* bu      = (const float*)d_in[2];
    const float* bv      = (const float*)d_in[3];
    const float* memory  = (const float*)d_in[4];
    const float* W_qkv   = (const float*)d_in[5];
    const float* W_rel   = (const float*)d_in[6];
    const float* W_o     = (const float*)d_in[7];
    const float* gamma   = (const float*)d_in[8];
    const float* beta    = (const float*)d_in[9];
    float* out = (float*)d_out;

    const int SM_BIG = 128*272 + 128*272 + 128*129*4;  // 135680 (modes 0,1,5)
    const int SM_AB  = 128*144 + 128*144 + 128*129*4;  // 102912 (mode 3)

    cudaFuncSetAttribute(gemm_tc<0>, cudaFuncAttributeMaxDynamicSharedMemorySize, SM_BIG);
    cudaFuncSetAttribute(gemm_tc<1>, cudaFuncAttributeMaxDynamicSharedMemorySize, SM_BIG);
    cudaFuncSetAttribute(gemm_tc<3>, cudaFuncAttributeMaxDynamicSharedMemorySize, SM_AB);
    cudaFuncSetAttribute(gemm_tc<5>, cudaFuncAttributeMaxDynamicSharedMemorySize, SM_BIG);

    conv_c<<<8192, 256>>>(memory, x);
    conv_pos<<<2048, 256>>>(pos_emb);
    transpose_bf<<<dim3(96, 32), 256>>>(W_qkv, 0, 3072);
    transpose_bf<<<dim3(32, 32), 256>>>(W_rel, 1, 1024);
    transpose_bf<<<dim3(32, 32), 256>>>(W_o,   2, 1024);

    gemm_tc<0><<<dim3(24, 64),    256, SM_BIG>>>(bu, bv);            // QKV
    gemm_tc<1><<<dim3(8, 16),     256, SM_BIG>>>(nullptr, nullptr);  // REL
    gemm_tc<3><<<dim3(16, 8, 64), 256, SM_AB>>>(nullptr, nullptr);   // BD -> shifted bf16
    flash_attn<<<dim3(8, 64), 256>>>();                              // AC+softmax+PV fused
    gemm_tc<5><<<dim3(8, 32),     256, SM_BIG>>>(nullptr, nullptr);  // OUT
    ln_kernel<<<4096, 256>>>(x, gamma, beta, out);
}